// round 4
// baseline (speedup 1.0000x reference)
#include <cuda_runtime.h>

#define NN  100000
#define EE  3200000
#define FIN 256
#define HID 16
#define CC  40
#define NB_SCAN 98   // ceil(100000/1024)

// ---------------- scratch (device globals; no allocation) ----------------
__device__ int   g_deg[NN];
__device__ float g_dinv[NN];
__device__ int   g_rowptr[NN + 1];
__device__ int   g_cursor[NN];
__device__ int   g_col[EE];
__device__ float g_P[NN * HID];   // dinv-scaled x@W1
__device__ float g_H[NN * HID];   // dinv-scaled relu hidden
__device__ float g_G[NN * HID];   // pre-W2 aggregated features
__device__ int   g_bsum[NB_SCAN];
__device__ int   g_is64;

// ---------------- helpers ----------------
__device__ __forceinline__ float4 f4add(float4 a, float4 b) {
    a.x += b.x; a.y += b.y; a.z += b.z; a.w += b.w; return a;
}

// ---------------- edge dtype detection (int64 vs int32) ----------------
// int64 little-endian nonneg values < 2^31 => every odd 32-bit word is 0.
__global__ void k_detect(const int* __restrict__ p) {
    if (blockIdx.x == 0 && threadIdx.x == 0) {
        int z = 0;
        #pragma unroll
        for (int k = 1; k < 64; k += 2) z |= p[k];
        g_is64 = (z == 0) ? 1 : 0;
    }
}

__global__ void k_zero() {
    int i = blockIdx.x * blockDim.x + threadIdx.x;
    if (i < NN) g_deg[i] = 0;
}

__global__ void k_deg(const void* __restrict__ eip) {
    int e = blockIdx.x * blockDim.x + threadIdx.x;
    if (e >= EE) return;
    int d;
    if (g_is64) d = (int)((const long long*)eip)[EE + e];
    else        d = ((const int*)eip)[EE + e];
    atomicAdd(&g_deg[d], 1);
}

// block-local inclusive scan of degrees; writes block-exclusive into g_cursor
__global__ void k_scan1() {
    __shared__ int ss[1024];
    int t = threadIdx.x;
    int i = blockIdx.x * 1024 + t;
    int d = (i < NN) ? g_deg[i] : 0;
    ss[t] = d;
    #pragma unroll
    for (int off = 1; off < 1024; off <<= 1) {
        __syncthreads();
        int v = (t >= off) ? ss[t - off] : 0;
        __syncthreads();
        ss[t] += v;
    }
    if (i < NN) g_cursor[i] = ss[t] - d;
    if (t == 1023) g_bsum[blockIdx.x] = ss[1023];
}

__global__ void k_scan2() {
    // tiny (98 elements) — single thread
    int run = 0;
    for (int b = 0; b < NB_SCAN; b++) { int v = g_bsum[b]; g_bsum[b] = run; run += v; }
    g_rowptr[NN] = run;  // == EE
}

__global__ void k_scan3() {
    int i = blockIdx.x * blockDim.x + threadIdx.x;
    if (i < NN) {
        int s = g_cursor[i] + g_bsum[i >> 10];
        g_rowptr[i] = s;
        g_cursor[i] = s;
        g_dinv[i]   = rsqrtf((float)g_deg[i] + 1.0f);  // +1 self-loop
    }
}

__global__ void k_fill(const void* __restrict__ eip) {
    int e = blockIdx.x * blockDim.x + threadIdx.x;
    if (e >= EE) return;
    int s, d;
    if (g_is64) {
        s = (int)((const long long*)eip)[e];
        d = (int)((const long long*)eip)[EE + e];
    } else {
        s = ((const int*)eip)[e];
        d = ((const int*)eip)[EE + e];
    }
    int p = atomicAdd(&g_cursor[d], 1);
    g_col[p] = s;
}

// ---------------- GEMM: g_P = dinv * (x @ W1), [N,16] ----------------
// 32 rows/block, 128 threads: thread = (row, 4-col group). SMEM-tiled, float4.
__global__ void __launch_bounds__(128) k_gemm(const float* __restrict__ x,
                                              const float* __restrict__ W1) {
    __shared__ float xs[32 * 260];     // 260-float pitch: conflict-free float4 LDS
    __shared__ float ws[FIN * HID];
    int tid  = threadIdx.x;
    int base = blockIdx.x * 32;

    float4* ws4 = (float4*)ws;
    const float4* W14 = (const float4*)W1;
    #pragma unroll
    for (int q = tid; q < FIN * HID / 4; q += 128) ws4[q] = W14[q];

    const float4* x4 = (const float4*)x;
    #pragma unroll
    for (int q = tid; q < 32 * 64; q += 128) {
        int r = q >> 6, qi = q & 63;
        *(float4*)&xs[r * 260 + qi * 4] = x4[(size_t)(base + r) * 64 + qi];
    }
    __syncthreads();

    int jg = tid & 3, r = tid >> 2;
    const float4* xr = (const float4*)xs + (size_t)r * 65;
    float4 acc = make_float4(0.f, 0.f, 0.f, 0.f);
    #pragma unroll 4
    for (int k4 = 0; k4 < 64; k4++) {
        float4 xv = xr[k4];
        float4 w0 = ws4[(k4 * 4 + 0) * 4 + jg];
        float4 w1 = ws4[(k4 * 4 + 1) * 4 + jg];
        float4 w2 = ws4[(k4 * 4 + 2) * 4 + jg];
        float4 w3 = ws4[(k4 * 4 + 3) * 4 + jg];
        acc.x += xv.x * w0.x + xv.y * w1.x + xv.z * w2.x + xv.w * w3.x;
        acc.y += xv.x * w0.y + xv.y * w1.y + xv.z * w2.y + xv.w * w3.y;
        acc.z += xv.x * w0.z + xv.y * w1.z + xv.z * w2.z + xv.w * w3.z;
        acc.w += xv.x * w0.w + xv.y * w1.w + xv.z * w2.w + xv.w * w3.w;
    }
    int row = base + r;           // grid is exact: 3125*32 == NN
    float s = g_dinv[row];
    acc.x *= s; acc.y *= s; acc.z *= s; acc.w *= s;
    ((float4*)g_P)[(size_t)row * 4 + jg] = acc;
}

// ---------------- Aggregation over CSR (dst-grouped) ----------------
// MODE 1: H' = dinv * relu(dinv*(sum P'[col] + P'[i]) + b1)   (P' pre-scaled)
// MODE 2: G  = dinv * (sum H'[col] + H'[i])
// 64 nodes/block, 256 threads: thread = (node, 4-feature quad).
template <int MODE>
__global__ void __launch_bounds__(256) k_agg(const float* __restrict__ bias) {
    const float4* in4 = (const float4*)(MODE == 1 ? (const float*)g_P : (const float*)g_H);
    float4*      out4 = (float4*)(MODE == 1 ? g_H : g_G);
    int tid = threadIdx.x;
    int c = tid & 3, ln = tid >> 2;
    int i = blockIdx.x * 64 + ln;
    if (i >= NN) return;

    int e  = g_rowptr[i];
    int e1 = g_rowptr[i + 1];
    float4 a0 = in4[(size_t)i * 4 + c];            // self-loop term (pre-scaled)
    float4 a1 = make_float4(0.f, 0.f, 0.f, 0.f);
    for (; e + 1 < e1; e += 2) {
        int sA = g_col[e], sB = g_col[e + 1];
        a0 = f4add(a0, in4[(size_t)sA * 4 + c]);
        a1 = f4add(a1, in4[(size_t)sB * 4 + c]);
    }
    if (e < e1) {
        int sA = g_col[e];
        a0 = f4add(a0, in4[(size_t)sA * 4 + c]);
    }
    float di = g_dinv[i];
    float4 v;
    v.x = (a0.x + a1.x) * di;
    v.y = (a0.y + a1.y) * di;
    v.z = (a0.z + a1.z) * di;
    v.w = (a0.w + a1.w) * di;
    if (MODE == 1) {
        float4 b = ((const float4*)bias)[c];
        v.x = fmaxf(v.x + b.x, 0.f) * di;
        v.y = fmaxf(v.y + b.y, 0.f) * di;
        v.z = fmaxf(v.z + b.z, 0.f) * di;
        v.w = fmaxf(v.w + b.w, 0.f) * di;
    }
    out4[(size_t)i * 4 + c] = v;
}

// ---------------- logits = G@W2 + b2 ; log_softmax ; coalesced store ----------------
__global__ void __launch_bounds__(64) k_final(const float* __restrict__ W2,
                                              const float* __restrict__ b2,
                                              float* __restrict__ out) {
    __shared__ float w2s[HID * CC];
    __shared__ float b2s[CC];
    __shared__ float lg[64 * CC];
    int tid = threadIdx.x;
    for (int q = tid; q < HID * CC; q += 64) w2s[q] = W2[q];
    if (tid < CC) b2s[tid] = b2[tid];
    __syncthreads();

    int i = blockIdx.x * 64 + tid;
    if (i < NN) {
        float a[CC];
        #pragma unroll
        for (int j = 0; j < CC; j++) a[j] = b2s[j];
        const float* g = &g_G[(size_t)i * HID];
        #pragma unroll
        for (int f = 0; f < HID; f++) {
            float gf = g[f];
            #pragma unroll
            for (int j = 0; j < CC; j++) a[j] += gf * w2s[f * CC + j];
        }
        float m = a[0];
        #pragma unroll
        for (int j = 1; j < CC; j++) m = fmaxf(m, a[j]);
        float s = 0.f;
        #pragma unroll
        for (int j = 0; j < CC; j++) s += __expf(a[j] - m);
        float lse = m + __logf(s);
        #pragma unroll
        for (int j = 0; j < CC; j++) lg[tid * CC + j] = a[j] - lse;
    } else {
        #pragma unroll
        for (int j = 0; j < CC; j++) lg[tid * CC + j] = 0.f;
    }
    __syncthreads();

    size_t base4 = (size_t)blockIdx.x * (64 * CC / 4);
    const float4* lg4 = (const float4*)lg;
    float4* o4 = (float4*)out;
    for (int q = tid; q < 64 * CC / 4; q += 64) {
        size_t o = base4 + q;
        if (o < (size_t)NN * CC / 4) o4[o] = lg4[q];
    }
}

// ---------------- launch ----------------
extern "C" void kernel_launch(void* const* d_in, const int* in_sizes, int n_in,
                              void* d_out, int out_size) {
    const float* x  = (const float*)d_in[0];
    const void*  ei = (const void*)d_in[1];   // int64 or int32, detected on device
    const float* W1 = (const float*)d_in[2];
    const float* b1 = (const float*)d_in[3];
    const float* W2 = (const float*)d_in[4];
    const float* b2 = (const float*)d_in[5];
    float* out = (float*)d_out;

    k_detect<<<1, 32>>>((const int*)ei);
    k_zero<<<(NN + 511) / 512, 512>>>();
    k_deg<<<(EE + 255) / 256, 256>>>(ei);
    k_scan1<<<NB_SCAN, 1024>>>();
    k_scan2<<<1, 1>>>();
    k_scan3<<<(NN + 511) / 512, 512>>>();
    k_fill<<<(EE + 255) / 256, 256>>>(ei);
    k_gemm<<<NN / 32, 128>>>(x, W1);
    k_agg<1><<<(NN + 63) / 64, 256>>>(b1);
    k_agg<2><<<(NN + 63) / 64, 256>>>(nullptr);
    k_final<<<(NN + 63) / 64, 64>>>(W2, b2, out);
}

// round 5
// speedup vs baseline: 1.0260x; 1.0260x over previous
#include <cuda_runtime.h>

#define NN  100000
#define EE  3200000
#define FIN 256
#define HID 16
#define CC  40
#define NB_SCAN 98   // ceil(100000/1024)

// ---------------- scratch (device globals; no allocation) ----------------
__device__ int   g_deg[NN];
__device__ float g_dinv[NN];
__device__ int   g_rowptr[NN + 1];
__device__ int   g_cursor[NN];
__device__ int   g_col[EE];
__device__ float g_P[NN * HID];   // dinv-scaled x@W1
__device__ float g_H[NN * HID];   // dinv-scaled relu hidden
__device__ float g_G[NN * HID];   // pre-W2 aggregated features
__device__ int   g_bsum[NB_SCAN];
__device__ int   g_is64;

// ---------------- helpers ----------------
__device__ __forceinline__ float4 f4add(float4 a, float4 b) {
    a.x += b.x; a.y += b.y; a.z += b.z; a.w += b.w; return a;
}

// ---------------- init: zero degrees + edge dtype detection ----------------
// int64 little-endian nonneg values < 2^31 => every odd 32-bit word is 0.
__global__ void k_init(const int* __restrict__ p) {
    int i = blockIdx.x * blockDim.x + threadIdx.x;
    if (i < NN) g_deg[i] = 0;
    if (i == 0) {
        int z = 0;
        #pragma unroll
        for (int k = 1; k < 64; k += 2) z |= p[k];
        g_is64 = (z == 0) ? 1 : 0;
    }
}

// ---------------- degree count: 2 edges per thread, vector loads ----------------
__global__ void k_deg(const void* __restrict__ eip) {
    int t = blockIdx.x * blockDim.x + threadIdx.x;   // t < EE/2
    if (t >= EE / 2) return;
    if (g_is64) {
        longlong2 v = ((const longlong2*)((const long long*)eip + EE))[t];
        atomicAdd(&g_deg[(int)v.x], 1);
        atomicAdd(&g_deg[(int)v.y], 1);
    } else {
        int2 v = ((const int2*)((const int*)eip + EE))[t];
        atomicAdd(&g_deg[v.x], 1);
        atomicAdd(&g_deg[v.y], 1);
    }
}

// ---------------- block scan (warp-shuffle based) ----------------
// writes block-exclusive prefix into g_cursor, block total into g_bsum
__global__ void __launch_bounds__(1024) k_scan1() {
    __shared__ int wsum[32];
    int t = threadIdx.x;
    int i = blockIdx.x * 1024 + t;
    int d = (i < NN) ? g_deg[i] : 0;
    int v = d;
    #pragma unroll
    for (int off = 1; off < 32; off <<= 1) {
        int n = __shfl_up_sync(0xffffffffu, v, off);
        if ((t & 31) >= off) v += n;
    }
    if ((t & 31) == 31) wsum[t >> 5] = v;
    __syncthreads();
    if (t < 32) {
        int w = wsum[t];
        #pragma unroll
        for (int off = 1; off < 32; off <<= 1) {
            int n = __shfl_up_sync(0xffffffffu, w, off);
            if (t >= off) w += n;
        }
        wsum[t] = w;
    }
    __syncthreads();
    int base = (t >= 32) ? wsum[(t >> 5) - 1] : 0;
    int incl = v + base;
    if (i < NN) g_cursor[i] = incl - d;
    if (t == 1023) g_bsum[blockIdx.x] = incl;
}

// ---------------- scan finalize: fold block-sum prefix, compute dinv ----------------
// block covers 512 nodes; (i>>10) is constant == blockIdx>>1 within the block.
__global__ void __launch_bounds__(512) k_scan3() {
    __shared__ int sbase;
    int b = blockIdx.x;
    if (threadIdx.x == 0) {
        int chunk = b >> 1;
        int s = 0;
        for (int j = 0; j < chunk; j++) s += g_bsum[j];
        sbase = s;
    }
    __syncthreads();
    int i = b * 512 + threadIdx.x;
    if (i < NN) {
        int s = g_cursor[i] + sbase;
        g_rowptr[i] = s;
        g_cursor[i] = s;
        g_dinv[i]   = rsqrtf((float)g_deg[i] + 1.0f);  // +1 self-loop
        if (i == NN - 1) g_rowptr[NN] = s + g_deg[i];  // == EE
    }
}

// ---------------- CSR fill: 2 edges per thread, vector loads ----------------
__global__ void k_fill(const void* __restrict__ eip) {
    int t = blockIdx.x * blockDim.x + threadIdx.x;   // t < EE/2
    if (t >= EE / 2) return;
    if (g_is64) {
        longlong2 s = ((const longlong2*)eip)[t];
        longlong2 d = ((const longlong2*)((const long long*)eip + EE))[t];
        int p0 = atomicAdd(&g_cursor[(int)d.x], 1);
        g_col[p0] = (int)s.x;
        int p1 = atomicAdd(&g_cursor[(int)d.y], 1);
        g_col[p1] = (int)s.y;
    } else {
        int2 s = ((const int2*)eip)[t];
        int2 d = ((const int2*)((const int*)eip + EE))[t];
        int p0 = atomicAdd(&g_cursor[d.x], 1);
        g_col[p0] = s.x;
        int p1 = atomicAdd(&g_cursor[d.y], 1);
        g_col[p1] = s.y;
    }
}

// ---------------- GEMM: g_P = dinv * (x @ W1), [N,16] ----------------
// 32 rows/block, 128 threads: thread = (row, 4-col group). SMEM-tiled, float4.
__global__ void __launch_bounds__(128) k_gemm(const float* __restrict__ x,
                                              const float* __restrict__ W1) {
    __shared__ float xs[32 * 260];     // 260-float pitch: conflict-free float4 LDS
    __shared__ float ws[FIN * HID];
    int tid  = threadIdx.x;
    int base = blockIdx.x * 32;

    float4* ws4 = (float4*)ws;
    const float4* W14 = (const float4*)W1;
    #pragma unroll
    for (int q = tid; q < FIN * HID / 4; q += 128) ws4[q] = W14[q];

    const float4* x4 = (const float4*)x;
    #pragma unroll
    for (int q = tid; q < 32 * 64; q += 128) {
        int r = q >> 6, qi = q & 63;
        *(float4*)&xs[r * 260 + qi * 4] = x4[(size_t)(base + r) * 64 + qi];
    }
    __syncthreads();

    int jg = tid & 3, r = tid >> 2;
    const float4* xr = (const float4*)xs + (size_t)r * 65;
    float4 acc = make_float4(0.f, 0.f, 0.f, 0.f);
    #pragma unroll 4
    for (int k4 = 0; k4 < 64; k4++) {
        float4 xv = xr[k4];
        float4 w0 = ws4[(k4 * 4 + 0) * 4 + jg];
        float4 w1 = ws4[(k4 * 4 + 1) * 4 + jg];
        float4 w2 = ws4[(k4 * 4 + 2) * 4 + jg];
        float4 w3 = ws4[(k4 * 4 + 3) * 4 + jg];
        acc.x += xv.x * w0.x + xv.y * w1.x + xv.z * w2.x + xv.w * w3.x;
        acc.y += xv.x * w0.y + xv.y * w1.y + xv.z * w2.y + xv.w * w3.y;
        acc.z += xv.x * w0.z + xv.y * w1.z + xv.z * w2.z + xv.w * w3.z;
        acc.w += xv.x * w0.w + xv.y * w1.w + xv.z * w2.w + xv.w * w3.w;
    }
    int row = base + r;           // grid is exact: 3125*32 == NN
    float s = g_dinv[row];
    acc.x *= s; acc.y *= s; acc.z *= s; acc.w *= s;
    ((float4*)g_P)[(size_t)row * 4 + jg] = acc;
}

// ---------------- Aggregation over CSR (dst-grouped), warp-per-node ----------------
// lane = 8 edge-lanes (el) x 4 feature-quads (c); shfl-down reduce over el.
// MODE 1: H' = dinv * relu(dinv*(sum P'[col] + P'[i]) + b1)   (P' pre-scaled)
// MODE 2: G  = dinv * (sum H'[col] + H'[i])
template <int MODE>
__global__ void __launch_bounds__(256) k_agg(const float* __restrict__ bias) {
    const float4* in4 = (const float4*)(MODE == 1 ? (const float*)g_P : (const float*)g_H);
    float4*      out4 = (float4*)(MODE == 1 ? g_H : g_G);
    int warp = threadIdx.x >> 5;
    int lane = threadIdx.x & 31;
    int el = lane >> 2, c = lane & 3;
    int i = blockIdx.x * 8 + warp;
    if (i >= NN) return;

    int e0 = g_rowptr[i];
    int e1 = g_rowptr[i + 1];
    float4 acc = make_float4(0.f, 0.f, 0.f, 0.f);
    for (int e = e0 + el; e < e1; e += 8) {
        int s = g_col[e];
        acc = f4add(acc, in4[(size_t)s * 4 + c]);
    }
    #pragma unroll
    for (int off = 16; off >= 4; off >>= 1) {
        acc.x += __shfl_down_sync(0xffffffffu, acc.x, off);
        acc.y += __shfl_down_sync(0xffffffffu, acc.y, off);
        acc.z += __shfl_down_sync(0xffffffffu, acc.z, off);
        acc.w += __shfl_down_sync(0xffffffffu, acc.w, off);
    }
    if (el == 0) {
        acc = f4add(acc, in4[(size_t)i * 4 + c]);   // self-loop (pre-scaled)
        float di = g_dinv[i];
        float4 v;
        v.x = acc.x * di; v.y = acc.y * di; v.z = acc.z * di; v.w = acc.w * di;
        if (MODE == 1) {
            float4 b = ((const float4*)bias)[c];
            v.x = fmaxf(v.x + b.x, 0.f) * di;
            v.y = fmaxf(v.y + b.y, 0.f) * di;
            v.z = fmaxf(v.z + b.z, 0.f) * di;
            v.w = fmaxf(v.w + b.w, 0.f) * di;
        }
        out4[(size_t)i * 4 + c] = v;
    }
}

// ---------------- logits = G@W2 + b2 ; log_softmax ; coalesced store ----------------
__global__ void __launch_bounds__(256) k_final(const float* __restrict__ W2,
                                               const float* __restrict__ b2,
                                               float* __restrict__ out) {
    __shared__ float w2s[HID * CC];
    __shared__ float b2s[CC];
    __shared__ float lg[256 * CC];
    int tid = threadIdx.x;
    for (int q = tid; q < HID * CC; q += 256) w2s[q] = W2[q];
    if (tid < CC) b2s[tid] = b2[tid];
    __syncthreads();

    int i = blockIdx.x * 256 + tid;
    if (i < NN) {
        float a[CC];
        #pragma unroll
        for (int j = 0; j < CC; j++) a[j] = b2s[j];
        const float* g = &g_G[(size_t)i * HID];
        #pragma unroll
        for (int f = 0; f < HID; f++) {
            float gf = g[f];
            #pragma unroll
            for (int j = 0; j < CC; j++) a[j] += gf * w2s[f * CC + j];
        }
        float m = a[0];
        #pragma unroll
        for (int j = 1; j < CC; j++) m = fmaxf(m, a[j]);
        float s = 0.f;
        #pragma unroll
        for (int j = 0; j < CC; j++) s += __expf(a[j] - m);
        float lse = m + __logf(s);
        #pragma unroll
        for (int j = 0; j < CC; j++) lg[tid * CC + j] = a[j] - lse;
    } else {
        #pragma unroll
        for (int j = 0; j < CC; j++) lg[tid * CC + j] = 0.f;
    }
    __syncthreads();

    size_t base4 = (size_t)blockIdx.x * (256 * CC / 4);
    const float4* lg4 = (const float4*)lg;
    float4* o4 = (float4*)out;
    for (int q = tid; q < 256 * CC / 4; q += 256) {
        size_t o = base4 + q;
        if (o < (size_t)NN * CC / 4) o4[o] = lg4[q];
    }
}

// ---------------- launch ----------------
extern "C" void kernel_launch(void* const* d_in, const int* in_sizes, int n_in,
                              void* d_out, int out_size) {
    const float* x  = (const float*)d_in[0];
    const void*  ei = (const void*)d_in[1];   // int64 or int32, detected on device
    const float* W1 = (const float*)d_in[2];
    const float* b1 = (const float*)d_in[3];
    const float* W2 = (const float*)d_in[4];
    const float* b2 = (const float*)d_in[5];
    float* out = (float*)d_out;

    k_init<<<(NN + 511) / 512, 512>>>((const int*)ei);
    k_deg<<<(EE / 2 + 255) / 256, 256>>>(ei);
    k_scan1<<<NB_SCAN, 1024>>>();
    k_scan3<<<(NN + 511) / 512, 512>>>();
    k_fill<<<(EE / 2 + 255) / 256, 256>>>(ei);
    k_gemm<<<NN / 32, 128>>>(x, W1);
    k_agg<1><<<(NN + 7) / 8, 256>>>(b1);
    k_agg<2><<<(NN + 7) / 8, 256>>>(nullptr);
    k_final<<<(NN + 255) / 256, 256>>>(W2, b2, out);
}

// round 7
// speedup vs baseline: 1.0306x; 1.0045x over previous
#include <cuda_runtime.h>

#define NN  100000
#define EE  3200000
#define FIN 256
#define HID 16
#define CC  40
#define NB_SCAN 98   // ceil(100000/1024)

// ---------------- scratch (device globals; no allocation) ----------------
__device__ int   g_deg[NN];
__device__ float g_dinv[NN];
__device__ int   g_rowptr[NN + 1];
__device__ int   g_cursor[NN];
__device__ int   g_col[EE];
__device__ float g_P[NN * HID];   // x@W1 (unscaled, then *= dinv in k_scaleP)
__device__ float g_H[NN * HID];   // dinv-scaled relu hidden
__device__ int   g_bsum[NB_SCAN];
__device__ int   g_is64;

// ---------------- helpers ----------------
__device__ __forceinline__ float4 f4add(float4 a, float4 b) {
    a.x += b.x; a.y += b.y; a.z += b.z; a.w += b.w; return a;
}

// ---------------- init: zero degrees + edge dtype detection ----------------
// int64 little-endian nonneg values < 2^31 => every odd 32-bit word is 0.
__global__ void k_init(const int* __restrict__ p) {
    int i = blockIdx.x * blockDim.x + threadIdx.x;
    if (i < NN) g_deg[i] = 0;
    if (i == 0) {
        int z = 0;
        #pragma unroll
        for (int k = 1; k < 64; k += 2) z |= p[k];
        g_is64 = (z == 0) ? 1 : 0;
    }
}

// ---------------- degree count: 2 edges per thread, vector loads ----------------
__global__ void k_deg(const void* __restrict__ eip) {
    int t = blockIdx.x * blockDim.x + threadIdx.x;   // t < EE/2
    if (t >= EE / 2) return;
    if (g_is64) {
        longlong2 v = ((const longlong2*)((const long long*)eip + EE))[t];
        atomicAdd(&g_deg[(int)v.x], 1);
        atomicAdd(&g_deg[(int)v.y], 1);
    } else {
        int2 v = ((const int2*)((const int*)eip + EE))[t];
        atomicAdd(&g_deg[v.x], 1);
        atomicAdd(&g_deg[v.y], 1);
    }
}

// ---------------- block scan (warp-shuffle based) ----------------
// writes block-exclusive prefix into g_cursor, block total into g_bsum
__global__ void __launch_bounds__(1024) k_scan1() {
    __shared__ int wsum[32];
    int t = threadIdx.x;
    int i = blockIdx.x * 1024 + t;
    int d = (i < NN) ? g_deg[i] : 0;
    int v = d;
    #pragma unroll
    for (int off = 1; off < 32; off <<= 1) {
        int n = __shfl_up_sync(0xffffffffu, v, off);
        if ((t & 31) >= off) v += n;
    }
    if ((t & 31) == 31) wsum[t >> 5] = v;
    __syncthreads();
    if (t < 32) {
        int w = wsum[t];
        #pragma unroll
        for (int off = 1; off < 32; off <<= 1) {
            int n = __shfl_up_sync(0xffffffffu, w, off);
            if (t >= off) w += n;
        }
        wsum[t] = w;
    }
    __syncthreads();
    int base = (t >= 32) ? wsum[(t >> 5) - 1] : 0;
    int incl = v + base;
    if (i < NN) g_cursor[i] = incl - d;
    if (t == 1023) g_bsum[blockIdx.x] = incl;
}

// ---------------- scan of the 98 block sums (in place -> exclusive) ----------------
__global__ void __launch_bounds__(128) k_scan2() {
    __shared__ int ws[4];
    int t = threadIdx.x, lane = t & 31, w = t >> 5;
    int d = (t < NB_SCAN) ? g_bsum[t] : 0;
    int v = d;
    #pragma unroll
    for (int off = 1; off < 32; off <<= 1) {
        int n = __shfl_up_sync(0xffffffffu, v, off);
        if (lane >= off) v += n;
    }
    if (lane == 31) ws[w] = v;
    __syncthreads();
    if (t == 0) {
        int r = 0;
        #pragma unroll
        for (int j = 0; j < 4; j++) { int x = ws[j]; ws[j] = r; r += x; }
    }
    __syncthreads();
    v += ws[w];
    if (t < NB_SCAN) g_bsum[t] = v - d;   // exclusive prefix
}

// ---------------- scan finalize: rowptr, cursor, dinv ----------------
__global__ void __launch_bounds__(512) k_scan3() {
    int i = blockIdx.x * 512 + threadIdx.x;
    if (i < NN) {
        int s = g_cursor[i] + g_bsum[i >> 10];
        g_rowptr[i] = s;
        g_cursor[i] = s;
        g_dinv[i]   = rsqrtf((float)g_deg[i] + 1.0f);  // +1 self-loop
        if (i == NN - 1) g_rowptr[NN] = s + g_deg[i];  // == EE
    }
}

// ---------------- CSR fill: 2 edges per thread, vector loads ----------------
__global__ void k_fill(const void* __restrict__ eip) {
    int t = blockIdx.x * blockDim.x + threadIdx.x;   // t < EE/2
    if (t >= EE / 2) return;
    if (g_is64) {
        longlong2 s = ((const longlong2*)eip)[t];
        longlong2 d = ((const longlong2*)((const long long*)eip + EE))[t];
        int p0 = atomicAdd(&g_cursor[(int)d.x], 1);
        g_col[p0] = (int)s.x;
        int p1 = atomicAdd(&g_cursor[(int)d.y], 1);
        g_col[p1] = (int)s.y;
    } else {
        int2 s = ((const int2*)eip)[t];
        int2 d = ((const int2*)((const int*)eip + EE))[t];
        int p0 = atomicAdd(&g_cursor[d.x], 1);
        g_col[p0] = s.x;
        int p1 = atomicAdd(&g_cursor[d.y], 1);
        g_col[p1] = s.y;
    }
}

// ---------------- GEMM: g_P = x @ W1 (unscaled), [N,16] ----------------
// 32 rows/block, 128 threads: thread = (row, 4-col group). SMEM-tiled, float4.
// Runs on a forked stream concurrently with the degree/scan/fill chain.
__global__ void __launch_bounds__(128) k_gemm(const float* __restrict__ x,
                                              const float* __restrict__ W1) {
    __shared__ float xs[32 * 260];     // 260-float pitch: conflict-free float4 LDS
    __shared__ float ws[FIN * HID];
    int tid  = threadIdx.x;
    int base = blockIdx.x * 32;

    float4* ws4 = (float4*)ws;
    const float4* W14 = (const float4*)W1;
    #pragma unroll
    for (int q = tid; q < FIN * HID / 4; q += 128) ws4[q] = W14[q];

    const float4* x4 = (const float4*)x;
    #pragma unroll
    for (int q = tid; q < 32 * 64; q += 128) {
        int r = q >> 6, qi = q & 63;
        *(float4*)&xs[r * 260 + qi * 4] = x4[(size_t)(base + r) * 64 + qi];
    }
    __syncthreads();

    int jg = tid & 3, r = tid >> 2;
    const float4* xr = (const float4*)xs + (size_t)r * 65;
    float4 acc = make_float4(0.f, 0.f, 0.f, 0.f);
    #pragma unroll 4
    for (int k4 = 0; k4 < 64; k4++) {
        float4 xv = xr[k4];
        float4 w0 = ws4[(k4 * 4 + 0) * 4 + jg];
        float4 w1 = ws4[(k4 * 4 + 1) * 4 + jg];
        float4 w2 = ws4[(k4 * 4 + 2) * 4 + jg];
        float4 w3 = ws4[(k4 * 4 + 3) * 4 + jg];
        acc.x += xv.x * w0.x + xv.y * w1.x + xv.z * w2.x + xv.w * w3.x;
        acc.y += xv.x * w0.y + xv.y * w1.y + xv.z * w2.y + xv.w * w3.y;
        acc.z += xv.x * w0.z + xv.y * w1.z + xv.z * w2.z + xv.w * w3.z;
        acc.w += xv.x * w0.w + xv.y * w1.w + xv.z * w2.w + xv.w * w3.w;
    }
    int row = base + r;           // grid is exact: 3125*32 == NN
    ((float4*)g_P)[(size_t)row * 4 + jg] = acc;
}

// ---------------- P *= dinv (row broadcast); overlaps k_fill ----------------
__global__ void __launch_bounds__(512) k_scaleP() {
    int t = blockIdx.x * 512 + threadIdx.x;   // t < NN*4 (float4 index)
    if (t < NN * 4) {
        float di = g_dinv[t >> 2];
        float4 v = ((float4*)g_P)[t];
        v.x *= di; v.y *= di; v.z *= di; v.w *= di;
        ((float4*)g_P)[t] = v;
    }
}

// ---------------- Layer-1 aggregation (warp-per-node) ----------------
// H' = dinv * relu(dinv*(sum P'[col] + P'[i]) + b1)   (P' pre-scaled by dinv)
__global__ void __launch_bounds__(256) k_agg1(const float* __restrict__ bias) {
    const float4* in4 = (const float4*)g_P;
    float4*      out4 = (float4*)g_H;
    int warp = threadIdx.x >> 5;
    int lane = threadIdx.x & 31;
    int el = lane >> 2, c = lane & 3;
    int i = blockIdx.x * 8 + warp;        // grid exact: 12500*8 == NN

    int e0 = g_rowptr[i];
    int e1 = g_rowptr[i + 1];
    float4 acc = make_float4(0.f, 0.f, 0.f, 0.f);
    for (int e = e0 + el; e < e1; e += 8) {
        int s = g_col[e];
        acc = f4add(acc, in4[(size_t)s * 4 + c]);
    }
    #pragma unroll
    for (int off = 16; off >= 4; off >>= 1) {
        acc.x += __shfl_down_sync(0xffffffffu, acc.x, off);
        acc.y += __shfl_down_sync(0xffffffffu, acc.y, off);
        acc.z += __shfl_down_sync(0xffffffffu, acc.z, off);
        acc.w += __shfl_down_sync(0xffffffffu, acc.w, off);
    }
    if (el == 0) {
        acc = f4add(acc, in4[(size_t)i * 4 + c]);   // self-loop (pre-scaled)
        float di = g_dinv[i];
        float4 b = ((const float4*)bias)[c];
        float4 v;
        v.x = fmaxf(acc.x * di + b.x, 0.f) * di;
        v.y = fmaxf(acc.y * di + b.y, 0.f) * di;
        v.z = fmaxf(acc.z * di + b.z, 0.f) * di;
        v.w = fmaxf(acc.w * di + b.w, 0.f) * di;
        out4[(size_t)i * 4 + c] = v;
    }
}

// ---------------- Fused layer-2 agg + W2 + bias + log_softmax + store ----------------
// warp-per-node gather of H', then the same warp computes the 40 logits
// (lane j -> classes j and j+32 for j<8) and the log_softmax, storing to out.
__global__ void __launch_bounds__(256) k_agg2_final(const float* __restrict__ W2,
                                                    const float* __restrict__ b2,
                                                    float* __restrict__ out) {
    __shared__ float w2s[HID * CC];
    __shared__ float b2s[CC];
    __shared__ float gsm[8][16];
    int tid = threadIdx.x;
    for (int q = tid; q < HID * CC; q += 256) w2s[q] = W2[q];
    if (tid < CC) b2s[tid] = b2[tid];
    __syncthreads();

    int warp = tid >> 5, lane = tid & 31;
    int el = lane >> 2, c = lane & 3;
    int i = blockIdx.x * 8 + warp;        // grid exact

    const float4* in4 = (const float4*)g_H;
    int e0 = g_rowptr[i];
    int e1 = g_rowptr[i + 1];
    float4 acc = make_float4(0.f, 0.f, 0.f, 0.f);
    for (int e = e0 + el; e < e1; e += 8) {
        int s = g_col[e];
        acc = f4add(acc, in4[(size_t)s * 4 + c]);
    }
    #pragma unroll
    for (int off = 16; off >= 4; off >>= 1) {
        acc.x += __shfl_down_sync(0xffffffffu, acc.x, off);
        acc.y += __shfl_down_sync(0xffffffffu, acc.y, off);
        acc.z += __shfl_down_sync(0xffffffffu, acc.z, off);
        acc.w += __shfl_down_sync(0xffffffffu, acc.w, off);
    }
    if (el == 0) {
        acc = f4add(acc, in4[(size_t)i * 4 + c]);
        float di = g_dinv[i];
        gsm[warp][c * 4 + 0] = acc.x * di;
        gsm[warp][c * 4 + 1] = acc.y * di;
        gsm[warp][c * 4 + 2] = acc.z * di;
        gsm[warp][c * 4 + 3] = acc.w * di;
    }
    __syncwarp();

    float g[HID];
    #pragma unroll
    for (int f = 0; f < HID; f++) g[f] = gsm[warp][f];

    int j0 = lane;
    float a0 = b2s[j0];
    #pragma unroll
    for (int f = 0; f < HID; f++) a0 += g[f] * w2s[f * CC + j0];
    float a1 = -1e30f;
    if (lane < 8) {
        int j1 = lane + 32;
        a1 = b2s[j1];
        #pragma unroll
        for (int f = 0; f < HID; f++) a1 += g[f] * w2s[f * CC + j1];
    }

    float m = fmaxf(a0, a1);
    #pragma unroll
    for (int off = 16; off >= 1; off >>= 1)
        m = fmaxf(m, __shfl_xor_sync(0xffffffffu, m, off));
    float s = __expf(a0 - m) + ((lane < 8) ? __expf(a1 - m) : 0.f);
    #pragma unroll
    for (int off = 16; off >= 1; off >>= 1)
        s += __shfl_xor_sync(0xffffffffu, s, off);
    float lse = m + __logf(s);

    out[(size_t)i * CC + j0] = a0 - lse;
    if (lane < 8) out[(size_t)i * CC + lane + 32] = a1 - lse;
}

// ---------------- launch ----------------
extern "C" void kernel_launch(void* const* d_in, const int* in_sizes, int n_in,
                              void* d_out, int out_size) {
    const float* x  = (const float*)d_in[0];
    const void*  ei = (const void*)d_in[1];   // int64 or int32, detected on device
    const float* W1 = (const float*)d_in[2];
    const float* b1 = (const float*)d_in[3];
    const float* W2 = (const float*)d_in[4];
    const float* b2 = (const float*)d_in[5];
    float* out = (float*)d_out;

    // lazily created once (outside capture, during the correctness run)
    static cudaStream_t s2 = nullptr;
    static cudaEvent_t ev_fork = nullptr, ev_scan3 = nullptr, ev_scaled = nullptr;
    if (!s2) {
        cudaStreamCreateWithFlags(&s2, cudaStreamNonBlocking);
        cudaEventCreateWithFlags(&ev_fork,   cudaEventDisableTiming);
        cudaEventCreateWithFlags(&ev_scan3,  cudaEventDisableTiming);
        cudaEventCreateWithFlags(&ev_scaled, cudaEventDisableTiming);
    }

    // fork: gemm branch (independent of edge processing)
    cudaEventRecord(ev_fork, 0);
    cudaStreamWaitEvent(s2, ev_fork, 0);
    k_gemm<<<NN / 32, 128, 0, s2>>>(x, W1);

    // main branch: CSR construction
    k_init<<<(NN + 511) / 512, 512>>>((const int*)ei);
    k_deg<<<(EE / 2 + 255) / 256, 256>>>(ei);
    k_scan1<<<NB_SCAN, 1024>>>();
    k_scan2<<<1, 128>>>();
    k_scan3<<<(NN + 511) / 512, 512>>>();
    cudaEventRecord(ev_scan3, 0);
    k_fill<<<(EE / 2 + 255) / 256, 256>>>(ei);

    // scaleP on gemm branch (needs gemm + scan3), overlaps k_fill
    cudaStreamWaitEvent(s2, ev_scan3, 0);
    k_scaleP<<<(NN * 4 + 511) / 512, 512, 0, s2>>>();
    cudaEventRecord(ev_scaled, s2);
    cudaStreamWaitEvent(0, ev_scaled, 0);

    // join: aggregations
    k_agg1<<<NN / 8, 256>>>(b1);
    k_agg2_final<<<NN / 8, 256>>>(W2, b2, out);
}